// round 15
// baseline (speedup 1.0000x reference)
#include <cuda_runtime.h>
#include <cuda_fp16.h>

// ---------------------------------------------------------------------------
// WindowAttention: mma.sync(fp16 hi/lo x3) for QKV + proj, scalar attention.
//   head-split 2 CTAs/window, occ=2, 256 threads, sm_103 (no 'a' features)
//   R7 kernel verbatim — the proven 615us / 1.08e-6 configuration.
// ---------------------------------------------------------------------------

#define NWIN   2048
#define NTOK   64
#define DIM    128
#define ATT_SCALE 0.25f

typedef unsigned long long u64;
typedef unsigned int u32;

__device__ float g_rpb[8 * 64 * 64];   // [h][n][m]
__device__ float g_aff[512];           // [b][softplus_scale(128)|bias(128)]

// ---- packed f32x2 helpers (attention phase) -------------------------------
__device__ __forceinline__ u64 pack2(float lo, float hi) {
    u64 r; asm("mov.b64 %0, {%1,%2};" : "=l"(r) : "f"(lo), "f"(hi)); return r;
}
__device__ __forceinline__ float2 unpack2(u64 v) {
    float2 f; asm("mov.b64 {%0,%1}, %2;" : "=f"(f.x), "=f"(f.y) : "l"(v)); return f;
}
__device__ __forceinline__ void ffma2(u64& d, u64 a, u64 b) {
    asm("fma.rn.f32x2 %0, %1, %2, %3;" : "=l"(d) : "l"(a), "l"(b), "l"(d));
}

// ---- mma.sync helpers -----------------------------------------------------
__device__ __forceinline__ void mma16816(float* d, u32 a0, u32 a1, u32 a2, u32 a3,
                                         u32 b0, u32 b1) {
    asm volatile("mma.sync.aligned.m16n8k16.row.col.f32.f16.f16.f32 "
                 "{%0,%1,%2,%3}, {%4,%5,%6,%7}, {%8,%9}, {%0,%1,%2,%3};"
                 : "+f"(d[0]), "+f"(d[1]), "+f"(d[2]), "+f"(d[3])
                 : "r"(a0), "r"(a1), "r"(a2), "r"(a3), "r"(b0), "r"(b1));
}
// fp32 pair -> fp16 hi pair + fp16 lo (residual) pair, packed as u32
__device__ __forceinline__ void cvt_hl(float2 f, u32& h, u32& l) {
    __half2 hh = __float22half2_rn(f);
    float2 hb = __half22float2(hh);
    __half2 ll = __float22half2_rn(make_float2(f.x - hb.x, f.y - hb.y));
    h = *(u32*)&hh;
    l = *(u32*)&ll;
}

// ---- prep -----------------------------------------------------------------
__global__ void prep_kernel(const float* __restrict__ frame_type,
                            const float* __restrict__ table,
                            const float* __restrict__ aff_w1,
                            const float* __restrict__ aff_b1,
                            const float* __restrict__ aff_w2,
                            const int*   __restrict__ rel_index) {
    int tid = threadIdx.x, blk = blockIdx.x;
    if (blk < 128) {
        int idx = blk * 256 + tid;
        g_rpb[idx] = table[rel_index[idx & 4095] * 8 + (idx >> 12)];
    } else {
        int c = tid;
        for (int b = 0; b < 2; b++) {
            float hdn[16];
#pragma unroll
            for (int j = 0; j < 16; j++) {
                float a = aff_b1[j];
                a = fmaf(frame_type[b * 2 + 0], aff_w1[j * 2 + 0], a);
                a = fmaf(frame_type[b * 2 + 1], aff_w1[j * 2 + 1], a);
                hdn[j] = 1.f / (1.f + __expf(-a));
            }
            float ap = 0.f;
#pragma unroll
            for (int j = 0; j < 16; j++) ap = fmaf(hdn[j], aff_w2[c * 16 + j], ap);
            g_aff[b * 256 + c] = (c < 128)
                ? fmaxf(ap, 0.f) + log1pf(__expf(-fabsf(ap))) : ap;
        }
    }
}

// ---- SMEM layout (float offsets) ------------------------------------------
#define XSTR   132                  // x row stride
#define SM_X   0                    // x fp32 [64][132]; later aout [64][ASTR]
#define ASTR   68
#define SM_Q   8448
#define HSTR   1032
#define QREG   (4 * HSTR)
#define SM_K   (SM_Q + QREG)        // 12576
#define SM_V   (SM_K + QREG)
#define SM_WH  (SM_V + QREG)        // fp16 [192][24] = 2304 floats
#define WHF    2304
#define SM_WL  (SM_WH + WHF)
#define SMEM_FLOATS (SM_WL + WHF)   // 25440
#define SMEM_BYTES  (SMEM_FLOATS * 4)  // 101760

// ---- main fused kernel ----------------------------------------------------
__global__ __launch_bounds__(256, 2)
void win_attn_kernel(const float* __restrict__ x,
                     const float* __restrict__ mask,
                     const float* __restrict__ qkv_w,
                     const float* __restrict__ qkv_b,
                     const float* __restrict__ proj_w,
                     const float* __restrict__ proj_b,
                     float* __restrict__ out) {
    extern __shared__ float smem[];
    const int tid  = threadIdx.x;
    const int lane = tid & 31, wid = tid >> 5;
    const int g    = lane >> 2, t4 = lane & 3;
    const int bwin = blockIdx.x >> 1;
    const int cg   = blockIdx.x & 1;      // head-group (heads 4cg..4cg+3)
    const int bat  = bwin >> 10;
    const int w    = bwin & 1023;
    __half* wh = (__half*)(smem + SM_WH);
    __half* wl = (__half*)(smem + SM_WL);

    // ---- load x tile (64x128, stride 132) -------------------------------
    for (int i = tid; i < 64 * 32; i += 256) {
        int row = i >> 5, c = (i & 31) << 2;
        *(float4*)(smem + SM_X + row * XSTR + c) =
            *(const float4*)(x + (size_t)bwin * 64 * DIM + row * DIM + c);
    }

    // ---- phase 1: QKV GEMM via mma.sync, 64 x 192 x 128 -----------------
    const int mi = wid & 3, nh = wid >> 2;   // warp: m-tile, n-half(96 cols)
    const int r0 = mi * 16 + g;              // fragment rows r0, r0+8
    float acc[12][4];
#pragma unroll
    for (int nt = 0; nt < 12; nt++)
#pragma unroll
        for (int q = 0; q < 4; q++) acc[nt][q] = 0.f;

    for (int kc = 0; kc < 8; kc++) {
        const int k0 = kc * 16;
        __syncthreads();
        // stage W chunk [192 cols][16 k] as fp16 hi/lo, row stride 24
#pragma unroll
        for (int it = 0; it < 3; it++) {
            int i4 = tid + it * 256;           // < 768
            int col = i4 >> 2, j4 = i4 & 3;
            int gcol = ((col >> 6) << 7) + 64 * cg + (col & 63);
            float4 v = *(const float4*)(qkv_w + gcol * DIM + k0 + 4 * j4);
            u32 h01, l01, h23, l23;
            cvt_hl(make_float2(v.x, v.y), h01, l01);
            cvt_hl(make_float2(v.z, v.w), h23, l23);
            *(uint2*)(wh + col * 24 + 4 * j4) = make_uint2(h01, h23);
            *(uint2*)(wl + col * 24 + 4 * j4) = make_uint2(l01, l23);
        }
        __syncthreads();
        // A fragments from x fp32
        u32 ah[4], al[4];
        {
            float2 f00 = *(const float2*)(smem + SM_X + r0 * XSTR + k0 + 2 * t4);
            float2 f10 = *(const float2*)(smem + SM_X + (r0 + 8) * XSTR + k0 + 2 * t4);
            float2 f01 = *(const float2*)(smem + SM_X + r0 * XSTR + k0 + 8 + 2 * t4);
            float2 f11 = *(const float2*)(smem + SM_X + (r0 + 8) * XSTR + k0 + 8 + 2 * t4);
            cvt_hl(f00, ah[0], al[0]); cvt_hl(f10, ah[1], al[1]);
            cvt_hl(f01, ah[2], al[2]); cvt_hl(f11, ah[3], al[3]);
        }
#pragma unroll
        for (int nt = 0; nt < 12; nt++) {
            const int col = nh * 96 + nt * 8 + g;
            u32 bh0 = *(const u32*)(wh + col * 24 + 2 * t4);
            u32 bh1 = *(const u32*)(wh + col * 24 + 2 * t4 + 8);
            u32 bl0 = *(const u32*)(wl + col * 24 + 2 * t4);
            u32 bl1 = *(const u32*)(wl + col * 24 + 2 * t4 + 8);
            mma16816(acc[nt], ah[0], ah[1], ah[2], ah[3], bh0, bh1);
            mma16816(acc[nt], ah[0], ah[1], ah[2], ah[3], bl0, bl1);
            mma16816(acc[nt], al[0], al[1], al[2], al[3], bh0, bh1);
        }
    }

    // ---- writeback q/k/v into [hl][n][d] SMEM ---------------------------
#pragma unroll
    for (int nt = 0; nt < 12; nt++) {
        const int col0 = nh * 96 + nt * 8 + 2 * t4;
        const int sec = col0 >> 6, cs = col0 & 63;
        const int hl = cs >> 4, d = cs & 15;
        const int gc = sec * 128 + 64 * cg + cs;
        const float2 bb = make_float2(qkv_b[gc], qkv_b[gc + 1]);
        float* base;
        if (sec == 0)      base = smem + SM_Q + hl * HSTR + d;
        else if (sec == 1) base = smem + SM_K + hl * HSTR + d;
        else               base = smem + SM_V + hl * HSTR + d;
        if (sec == 0) {
            *(float2*)(base + r0 * 16) = make_float2(
                (acc[nt][0] + bb.x) * ATT_SCALE, (acc[nt][1] + bb.y) * ATT_SCALE);
            *(float2*)(base + (r0 + 8) * 16) = make_float2(
                (acc[nt][2] + bb.x) * ATT_SCALE, (acc[nt][3] + bb.y) * ATT_SCALE);
        } else if (sec == 1) {
            *(float2*)(base + r0 * 16) = make_float2(acc[nt][0] + bb.x, acc[nt][1] + bb.y);
            *(float2*)(base + (r0 + 8) * 16) = make_float2(acc[nt][2] + bb.x, acc[nt][3] + bb.y);
        } else {
            const int c = 64 * cg + cs;
            const float s0 = g_aff[bat * 256 + c],     b0 = g_aff[bat * 256 + 128 + c];
            const float s1 = g_aff[bat * 256 + c + 1], b1 = g_aff[bat * 256 + 128 + c + 1];
            *(float2*)(base + r0 * 16) = make_float2(
                fmaf(s0, acc[nt][0] + bb.x, b0), fmaf(s1, acc[nt][1] + bb.y, b1));
            *(float2*)(base + (r0 + 8) * 16) = make_float2(
                fmaf(s0, acc[nt][2] + bb.x, b0), fmaf(s1, acc[nt][3] + bb.y, b1));
        }
    }
    __syncthreads();

    // ---- phase 2: attention (scalar, proven), aout -> SM_X --------------
    {
        const int hl = tid >> 6, n = tid & 63;
        const int hg = 4 * cg + hl;
        const ulonglong2* q4 = (const ulonglong2*)(smem + SM_Q + hl * HSTR + n * 16);
        u64 q2[8];
        {
            ulonglong2 a = q4[0], b = q4[1], c = q4[2], d = q4[3];
            q2[0] = a.x; q2[1] = a.y; q2[2] = b.x; q2[3] = b.y;
            q2[4] = c.x; q2[5] = c.y; q2[6] = d.x; q2[7] = d.y;
        }
        const float* rpbr = g_rpb + hg * 4096 + n * 64;
        const float* mr   = mask + (size_t)w * 4096 + n * 64;
        float s[64];
#pragma unroll
        for (int m4 = 0; m4 < 16; m4++) {
            float4 a = *(const float4*)(rpbr + 4 * m4);
            float4 b = *(const float4*)(mr + 4 * m4);
            s[4*m4+0] = a.x + b.x; s[4*m4+1] = a.y + b.y;
            s[4*m4+2] = a.z + b.z; s[4*m4+3] = a.w + b.w;
        }
        const char* kbase = (const char*)(smem + SM_K + hl * HSTR);
        float mxp[4] = {-1e30f, -1e30f, -1e30f, -1e30f};
#pragma unroll 16
        for (int m = 0; m < 64; m++) {
            const ulonglong2* kp = (const ulonglong2*)(kbase + m * 64);
            ulonglong2 ka = kp[0], kb = kp[1], kc2 = kp[2], kd = kp[3];
            u64 a2 = 0ULL, b2 = 0ULL;
            ffma2(a2, q2[0], ka.x);  ffma2(b2, q2[1], ka.y);
            ffma2(a2, q2[2], kb.x);  ffma2(b2, q2[3], kb.y);
            ffma2(a2, q2[4], kc2.x); ffma2(b2, q2[5], kc2.y);
            ffma2(a2, q2[6], kd.x);  ffma2(b2, q2[7], kd.y);
            float2 ra = unpack2(a2), rb = unpack2(b2);
            s[m] += (ra.x + ra.y) + (rb.x + rb.y);
            mxp[m & 3] = fmaxf(mxp[m & 3], s[m]);
        }
        const float mx = fmaxf(fmaxf(mxp[0], mxp[1]), fmaxf(mxp[2], mxp[3]));
        float sp[4] = {0.f, 0.f, 0.f, 0.f};
#pragma unroll
        for (int m = 0; m < 64; m++) {
            float p = __expf(s[m] - mx);
            s[m] = p; sp[m & 3] += p;
        }
        const float inv = 1.f / ((sp[0] + sp[1]) + (sp[2] + sp[3]));
        u64 o2[8];
#pragma unroll
        for (int i = 0; i < 8; i++) o2[i] = 0ULL;
        const char* vbase = (const char*)(smem + SM_V + hl * HSTR);
#pragma unroll 16
        for (int m = 0; m < 64; m++) {
            const ulonglong2* vp = (const ulonglong2*)(vbase + m * 64);
            ulonglong2 va = vp[0], vb = vp[1], vc = vp[2], vd = vp[3];
            u64 p2 = pack2(s[m], s[m]);
            ffma2(o2[0], p2, va.x); ffma2(o2[1], p2, va.y);
            ffma2(o2[2], p2, vb.x); ffma2(o2[3], p2, vb.y);
            ffma2(o2[4], p2, vc.x); ffma2(o2[5], p2, vc.y);
            ffma2(o2[6], p2, vd.x); ffma2(o2[7], p2, vd.y);
        }
        float* orow = smem + SM_X + n * ASTR + hl * 16;   // aout (x is dead)
#pragma unroll
        for (int i = 0; i < 8; i++) {
            float2 r = unpack2(o2[i]);
            *(float2*)(orow + 2 * i) = make_float2(r.x * inv, r.y * inv);
        }
    }

    // ---- phase 3: partial proj via mma.sync, 64 x 128 x 64 --------------
    float pacc[8][4];
#pragma unroll
    for (int nt = 0; nt < 8; nt++)
#pragma unroll
        for (int q = 0; q < 4; q++) pacc[nt][q] = 0.f;

    for (int kc = 0; kc < 4; kc++) {
        const int k0 = kc * 16;
        __syncthreads();     // aout complete (kc=0) / W chunk consumed
        // stage proj_w chunk [128 cols][16 k] fp16 hi/lo, stride 24
#pragma unroll
        for (int it = 0; it < 2; it++) {
            int i4 = tid + it * 256;           // < 512
            int c = i4 >> 2, j4 = i4 & 3;
            float4 v = *(const float4*)(proj_w + c * DIM + 64 * cg + k0 + 4 * j4);
            u32 h01, l01, h23, l23;
            cvt_hl(make_float2(v.x, v.y), h01, l01);
            cvt_hl(make_float2(v.z, v.w), h23, l23);
            *(uint2*)(wh + c * 24 + 4 * j4) = make_uint2(h01, h23);
            *(uint2*)(wl + c * 24 + 4 * j4) = make_uint2(l01, l23);
        }
        __syncthreads();
        // A fragments from aout
        u32 ah[4], al[4];
        {
            float2 f00 = *(const float2*)(smem + SM_X + r0 * ASTR + k0 + 2 * t4);
            float2 f10 = *(const float2*)(smem + SM_X + (r0 + 8) * ASTR + k0 + 2 * t4);
            float2 f01 = *(const float2*)(smem + SM_X + r0 * ASTR + k0 + 8 + 2 * t4);
            float2 f11 = *(const float2*)(smem + SM_X + (r0 + 8) * ASTR + k0 + 8 + 2 * t4);
            cvt_hl(f00, ah[0], al[0]); cvt_hl(f10, ah[1], al[1]);
            cvt_hl(f01, ah[2], al[2]); cvt_hl(f11, ah[3], al[3]);
        }
#pragma unroll
        for (int nt = 0; nt < 8; nt++) {
            const int col = nh * 64 + nt * 8 + g;     // out channel
            u32 bh0 = *(const u32*)(wh + col * 24 + 2 * t4);
            u32 bh1 = *(const u32*)(wh + col * 24 + 2 * t4 + 8);
            u32 bl0 = *(const u32*)(wl + col * 24 + 2 * t4);
            u32 bl1 = *(const u32*)(wl + col * 24 + 2 * t4 + 8);
            mma16816(pacc[nt], ah[0], ah[1], ah[2], ah[3], bh0, bh1);
            mma16816(pacc[nt], ah[0], ah[1], ah[2], ah[3], bl0, bl1);
            mma16816(pacc[nt], al[0], al[1], al[2], al[3], bh0, bh1);
        }
    }

    // split-k accumulate into zero-initialized out
    float* og = out + (size_t)bwin * 64 * DIM;
#pragma unroll
    for (int nt = 0; nt < 8; nt++) {
        const int c0 = nh * 64 + nt * 8 + 2 * t4;
        float2 bb = make_float2(0.f, 0.f);
        if (cg == 0) { bb.x = proj_b[c0]; bb.y = proj_b[c0 + 1]; }
        atomicAdd(&og[r0 * DIM + c0],           pacc[nt][0] + bb.x);
        atomicAdd(&og[r0 * DIM + c0 + 1],       pacc[nt][1] + bb.y);
        atomicAdd(&og[(r0 + 8) * DIM + c0],     pacc[nt][2] + bb.x);
        atomicAdd(&og[(r0 + 8) * DIM + c0 + 1], pacc[nt][3] + bb.y);
    }
}

// ---------------------------------------------------------------------------
extern "C" void kernel_launch(void* const* d_in, const int* in_sizes, int n_in,
                              void* d_out, int out_size) {
    const float* x          = (const float*)d_in[0];
    const float* mask       = (const float*)d_in[1];
    const float* frame_type = (const float*)d_in[2];
    const float* qkv_w      = (const float*)d_in[3];
    const float* qkv_b      = (const float*)d_in[4];
    const float* table      = (const float*)d_in[5];
    const float* proj_w     = (const float*)d_in[6];
    const float* proj_b     = (const float*)d_in[7];
    const float* aff_w1     = (const float*)d_in[8];
    const float* aff_b1     = (const float*)d_in[9];
    const float* aff_w2     = (const float*)d_in[10];
    const int*   rel_index  = (const int*)d_in[11];
    float* out = (float*)d_out;

    cudaFuncSetAttribute(win_attn_kernel,
                         cudaFuncAttributeMaxDynamicSharedMemorySize, SMEM_BYTES);

    cudaMemsetAsync(out, 0, (size_t)out_size * sizeof(float));
    prep_kernel<<<129, 256>>>(frame_type, table, aff_w1, aff_b1, aff_w2, rel_index);
    win_attn_kernel<<<NWIN * 2, 256, SMEM_BYTES>>>(x, mask, qkv_w, qkv_b,
                                                   proj_w, proj_b, out);
}

// round 16
// speedup vs baseline: 1.0126x; 1.0126x over previous
#include <cuda_runtime.h>
#include <cuda_fp16.h>

// ---------------------------------------------------------------------------
// WindowAttention: mma.sync(fp16 hi/lo x3) for QKV + proj, scalar attention.
//   head-split 2 CTAs/window, occ=2, 256 threads, sm_103 (no 'a' features)
//   R7 + register double-buffering of weight LDG (bit-identical math).
// ---------------------------------------------------------------------------

#define NWIN   2048
#define NTOK   64
#define DIM    128
#define ATT_SCALE 0.25f

typedef unsigned long long u64;
typedef unsigned int u32;

__device__ float g_rpb[8 * 64 * 64];   // [h][n][m]
__device__ float g_aff[512];           // [b][softplus_scale(128)|bias(128)]

// ---- packed f32x2 helpers (attention phase) -------------------------------
__device__ __forceinline__ u64 pack2(float lo, float hi) {
    u64 r; asm("mov.b64 %0, {%1,%2};" : "=l"(r) : "f"(lo), "f"(hi)); return r;
}
__device__ __forceinline__ float2 unpack2(u64 v) {
    float2 f; asm("mov.b64 {%0,%1}, %2;" : "=f"(f.x), "=f"(f.y) : "l"(v)); return f;
}
__device__ __forceinline__ void ffma2(u64& d, u64 a, u64 b) {
    asm("fma.rn.f32x2 %0, %1, %2, %3;" : "=l"(d) : "l"(a), "l"(b), "l"(d));
}

// ---- mma.sync helpers -----------------------------------------------------
__device__ __forceinline__ void mma16816(float* d, u32 a0, u32 a1, u32 a2, u32 a3,
                                         u32 b0, u32 b1) {
    asm volatile("mma.sync.aligned.m16n8k16.row.col.f32.f16.f16.f32 "
                 "{%0,%1,%2,%3}, {%4,%5,%6,%7}, {%8,%9}, {%0,%1,%2,%3};"
                 : "+f"(d[0]), "+f"(d[1]), "+f"(d[2]), "+f"(d[3])
                 : "r"(a0), "r"(a1), "r"(a2), "r"(a3), "r"(b0), "r"(b1));
}
// fp32 pair -> fp16 hi pair + fp16 lo (residual) pair, packed as u32
__device__ __forceinline__ void cvt_hl(float2 f, u32& h, u32& l) {
    __half2 hh = __float22half2_rn(f);
    float2 hb = __half22float2(hh);
    __half2 ll = __float22half2_rn(make_float2(f.x - hb.x, f.y - hb.y));
    h = *(u32*)&hh;
    l = *(u32*)&ll;
}

// ---- prep -----------------------------------------------------------------
__global__ void prep_kernel(const float* __restrict__ frame_type,
                            const float* __restrict__ table,
                            const float* __restrict__ aff_w1,
                            const float* __restrict__ aff_b1,
                            const float* __restrict__ aff_w2,
                            const int*   __restrict__ rel_index) {
    int tid = threadIdx.x, blk = blockIdx.x;
    if (blk < 128) {
        int idx = blk * 256 + tid;
        g_rpb[idx] = table[rel_index[idx & 4095] * 8 + (idx >> 12)];
    } else {
        int c = tid;
        for (int b = 0; b < 2; b++) {
            float hdn[16];
#pragma unroll
            for (int j = 0; j < 16; j++) {
                float a = aff_b1[j];
                a = fmaf(frame_type[b * 2 + 0], aff_w1[j * 2 + 0], a);
                a = fmaf(frame_type[b * 2 + 1], aff_w1[j * 2 + 1], a);
                hdn[j] = 1.f / (1.f + __expf(-a));
            }
            float ap = 0.f;
#pragma unroll
            for (int j = 0; j < 16; j++) ap = fmaf(hdn[j], aff_w2[c * 16 + j], ap);
            g_aff[b * 256 + c] = (c < 128)
                ? fmaxf(ap, 0.f) + log1pf(__expf(-fabsf(ap))) : ap;
        }
    }
}

// ---- SMEM layout (float offsets) ------------------------------------------
#define XSTR   132                  // x row stride
#define SM_X   0                    // x fp32 [64][132]; later aout [64][ASTR]
#define ASTR   68
#define SM_Q   8448
#define HSTR   1032
#define QREG   (4 * HSTR)
#define SM_K   (SM_Q + QREG)        // 12576
#define SM_V   (SM_K + QREG)
#define SM_WH  (SM_V + QREG)        // fp16 [192][24] = 2304 floats
#define WHF    2304
#define SM_WL  (SM_WH + WHF)
#define SMEM_FLOATS (SM_WL + WHF)   // 25440
#define SMEM_BYTES  (SMEM_FLOATS * 4)  // 101760

// ---- main fused kernel ----------------------------------------------------
__global__ __launch_bounds__(256, 2)
void win_attn_kernel(const float* __restrict__ x,
                     const float* __restrict__ mask,
                     const float* __restrict__ qkv_w,
                     const float* __restrict__ qkv_b,
                     const float* __restrict__ proj_w,
                     const float* __restrict__ proj_b,
                     float* __restrict__ out) {
    extern __shared__ float smem[];
    const int tid  = threadIdx.x;
    const int lane = tid & 31, wid = tid >> 5;
    const int g    = lane >> 2, t4 = lane & 3;
    const int bwin = blockIdx.x >> 1;
    const int cg   = blockIdx.x & 1;      // head-group (heads 4cg..4cg+3)
    const int bat  = bwin >> 10;
    const int w    = bwin & 1023;
    __half* wh = (__half*)(smem + SM_WH);
    __half* wl = (__half*)(smem + SM_WL);

    // per-thread W staging coordinates (constant across chunks)
    int wcol[3], wj4[3];
    const float* wsrc[3];
#pragma unroll
    for (int it = 0; it < 3; it++) {
        int i4 = tid + it * 256;           // < 768
        wcol[it] = i4 >> 2; wj4[it] = i4 & 3;
        int gcol = ((wcol[it] >> 6) << 7) + 64 * cg + (wcol[it] & 63);
        wsrc[it] = qkv_w + gcol * DIM + 4 * wj4[it];
    }

    // ---- load x tile (64x128, stride 132) -------------------------------
    for (int i = tid; i < 64 * 32; i += 256) {
        int row = i >> 5, c = (i & 31) << 2;
        *(float4*)(smem + SM_X + row * XSTR + c) =
            *(const float4*)(x + (size_t)bwin * 64 * DIM + row * DIM + c);
    }

    // prefetch W chunk 0
    float4 wreg[3];
#pragma unroll
    for (int it = 0; it < 3; it++) wreg[it] = *(const float4*)(wsrc[it]);

    // ---- phase 1: QKV GEMM via mma.sync, 64 x 192 x 128 -----------------
    const int mi = wid & 3, nh = wid >> 2;   // warp: m-tile, n-half(96 cols)
    const int r0 = mi * 16 + g;              // fragment rows r0, r0+8
    float acc[12][4];
#pragma unroll
    for (int nt = 0; nt < 12; nt++)
#pragma unroll
        for (int q = 0; q < 4; q++) acc[nt][q] = 0.f;

    for (int kc = 0; kc < 8; kc++) {
        const int k0 = kc * 16;
        __syncthreads();
        // store prefetched W chunk [192 cols][16 k] as fp16 hi/lo, stride 24
#pragma unroll
        for (int it = 0; it < 3; it++) {
            float4 v = wreg[it];
            u32 h01, l01, h23, l23;
            cvt_hl(make_float2(v.x, v.y), h01, l01);
            cvt_hl(make_float2(v.z, v.w), h23, l23);
            *(uint2*)(wh + wcol[it] * 24 + 4 * wj4[it]) = make_uint2(h01, h23);
            *(uint2*)(wl + wcol[it] * 24 + 4 * wj4[it]) = make_uint2(l01, l23);
        }
        __syncthreads();
        // prefetch next chunk (latency overlaps MMA below)
        if (kc < 7) {
#pragma unroll
            for (int it = 0; it < 3; it++)
                wreg[it] = *(const float4*)(wsrc[it] + (kc + 1) * 16);
        }
        // A fragments from x fp32
        u32 ah[4], al[4];
        {
            float2 f00 = *(const float2*)(smem + SM_X + r0 * XSTR + k0 + 2 * t4);
            float2 f10 = *(const float2*)(smem + SM_X + (r0 + 8) * XSTR + k0 + 2 * t4);
            float2 f01 = *(const float2*)(smem + SM_X + r0 * XSTR + k0 + 8 + 2 * t4);
            float2 f11 = *(const float2*)(smem + SM_X + (r0 + 8) * XSTR + k0 + 8 + 2 * t4);
            cvt_hl(f00, ah[0], al[0]); cvt_hl(f10, ah[1], al[1]);
            cvt_hl(f01, ah[2], al[2]); cvt_hl(f11, ah[3], al[3]);
        }
#pragma unroll
        for (int nt = 0; nt < 12; nt++) {
            const int col = nh * 96 + nt * 8 + g;
            u32 bh0 = *(const u32*)(wh + col * 24 + 2 * t4);
            u32 bh1 = *(const u32*)(wh + col * 24 + 2 * t4 + 8);
            u32 bl0 = *(const u32*)(wl + col * 24 + 2 * t4);
            u32 bl1 = *(const u32*)(wl + col * 24 + 2 * t4 + 8);
            mma16816(acc[nt], ah[0], ah[1], ah[2], ah[3], bh0, bh1);
            mma16816(acc[nt], ah[0], ah[1], ah[2], ah[3], bl0, bl1);
            mma16816(acc[nt], al[0], al[1], al[2], al[3], bh0, bh1);
        }
    }

    // ---- writeback q/k/v into [hl][n][d] SMEM ---------------------------
#pragma unroll
    for (int nt = 0; nt < 12; nt++) {
        const int col0 = nh * 96 + nt * 8 + 2 * t4;
        const int sec = col0 >> 6, cs = col0 & 63;
        const int hl = cs >> 4, d = cs & 15;
        const int gc = sec * 128 + 64 * cg + cs;
        const float2 bb = make_float2(qkv_b[gc], qkv_b[gc + 1]);
        float* base;
        if (sec == 0)      base = smem + SM_Q + hl * HSTR + d;
        else if (sec == 1) base = smem + SM_K + hl * HSTR + d;
        else               base = smem + SM_V + hl * HSTR + d;
        if (sec == 0) {
            *(float2*)(base + r0 * 16) = make_float2(
                (acc[nt][0] + bb.x) * ATT_SCALE, (acc[nt][1] + bb.y) * ATT_SCALE);
            *(float2*)(base + (r0 + 8) * 16) = make_float2(
                (acc[nt][2] + bb.x) * ATT_SCALE, (acc[nt][3] + bb.y) * ATT_SCALE);
        } else if (sec == 1) {
            *(float2*)(base + r0 * 16) = make_float2(acc[nt][0] + bb.x, acc[nt][1] + bb.y);
            *(float2*)(base + (r0 + 8) * 16) = make_float2(acc[nt][2] + bb.x, acc[nt][3] + bb.y);
        } else {
            const int c = 64 * cg + cs;
            const float s0 = g_aff[bat * 256 + c],     b0 = g_aff[bat * 256 + 128 + c];
            const float s1 = g_aff[bat * 256 + c + 1], b1 = g_aff[bat * 256 + 128 + c + 1];
            *(float2*)(base + r0 * 16) = make_float2(
                fmaf(s0, acc[nt][0] + bb.x, b0), fmaf(s1, acc[nt][1] + bb.y, b1));
            *(float2*)(base + (r0 + 8) * 16) = make_float2(
                fmaf(s0, acc[nt][2] + bb.x, b0), fmaf(s1, acc[nt][3] + bb.y, b1));
        }
    }
    __syncthreads();

    // ---- phase 2: attention (scalar, proven), aout -> SM_X --------------
    {
        const int hl = tid >> 6, n = tid & 63;
        const int hg = 4 * cg + hl;
        const ulonglong2* q4 = (const ulonglong2*)(smem + SM_Q + hl * HSTR + n * 16);
        u64 q2[8];
        {
            ulonglong2 a = q4[0], b = q4[1], c = q4[2], d = q4[3];
            q2[0] = a.x; q2[1] = a.y; q2[2] = b.x; q2[3] = b.y;
            q2[4] = c.x; q2[5] = c.y; q2[6] = d.x; q2[7] = d.y;
        }
        const float* rpbr = g_rpb + hg * 4096 + n * 64;
        const float* mr   = mask + (size_t)w * 4096 + n * 64;
        float s[64];
#pragma unroll
        for (int m4 = 0; m4 < 16; m4++) {
            float4 a = *(const float4*)(rpbr + 4 * m4);
            float4 b = *(const float4*)(mr + 4 * m4);
            s[4*m4+0] = a.x + b.x; s[4*m4+1] = a.y + b.y;
            s[4*m4+2] = a.z + b.z; s[4*m4+3] = a.w + b.w;
        }
        const char* kbase = (const char*)(smem + SM_K + hl * HSTR);
        float mxp[4] = {-1e30f, -1e30f, -1e30f, -1e30f};
#pragma unroll 16
        for (int m = 0; m < 64; m++) {
            const ulonglong2* kp = (const ulonglong2*)(kbase + m * 64);
            ulonglong2 ka = kp[0], kb = kp[1], kc2 = kp[2], kd = kp[3];
            u64 a2 = 0ULL, b2 = 0ULL;
            ffma2(a2, q2[0], ka.x);  ffma2(b2, q2[1], ka.y);
            ffma2(a2, q2[2], kb.x);  ffma2(b2, q2[3], kb.y);
            ffma2(a2, q2[4], kc2.x); ffma2(b2, q2[5], kc2.y);
            ffma2(a2, q2[6], kd.x);  ffma2(b2, q2[7], kd.y);
            float2 ra = unpack2(a2), rb = unpack2(b2);
            s[m] += (ra.x + ra.y) + (rb.x + rb.y);
            mxp[m & 3] = fmaxf(mxp[m & 3], s[m]);
        }
        const float mx = fmaxf(fmaxf(mxp[0], mxp[1]), fmaxf(mxp[2], mxp[3]));
        float sp[4] = {0.f, 0.f, 0.f, 0.f};
#pragma unroll
        for (int m = 0; m < 64; m++) {
            float p = __expf(s[m] - mx);
            s[m] = p; sp[m & 3] += p;
        }
        const float inv = 1.f / ((sp[0] + sp[1]) + (sp[2] + sp[3]));
        u64 o2[8];
#pragma unroll
        for (int i = 0; i < 8; i++) o2[i] = 0ULL;
        const char* vbase = (const char*)(smem + SM_V + hl * HSTR);
#pragma unroll 16
        for (int m = 0; m < 64; m++) {
            const ulonglong2* vp = (const ulonglong2*)(vbase + m * 64);
            ulonglong2 va = vp[0], vb = vp[1], vc = vp[2], vd = vp[3];
            u64 p2 = pack2(s[m], s[m]);
            ffma2(o2[0], p2, va.x); ffma2(o2[1], p2, va.y);
            ffma2(o2[2], p2, vb.x); ffma2(o2[3], p2, vb.y);
            ffma2(o2[4], p2, vc.x); ffma2(o2[5], p2, vc.y);
            ffma2(o2[6], p2, vd.x); ffma2(o2[7], p2, vd.y);
        }
        float* orow = smem + SM_X + n * ASTR + hl * 16;   // aout (x is dead)
#pragma unroll
        for (int i = 0; i < 8; i++) {
            float2 r = unpack2(o2[i]);
            *(float2*)(orow + 2 * i) = make_float2(r.x * inv, r.y * inv);
        }
    }

    // ---- phase 3: partial proj via mma.sync, 64 x 128 x 64 --------------
    float pacc[8][4];
#pragma unroll
    for (int nt = 0; nt < 8; nt++)
#pragma unroll
        for (int q = 0; q < 4; q++) pacc[nt][q] = 0.f;

    // per-thread proj staging coordinates + prefetch chunk 0
    int pc[2], pj4[2];
    const float* psrc[2];
#pragma unroll
    for (int it = 0; it < 2; it++) {
        int i4 = tid + it * 256;           // < 512
        pc[it] = i4 >> 2; pj4[it] = i4 & 3;
        psrc[it] = proj_w + pc[it] * DIM + 64 * cg + 4 * pj4[it];
    }
    float4 preg[2];
#pragma unroll
    for (int it = 0; it < 2; it++) preg[it] = *(const float4*)(psrc[it]);

    for (int kc = 0; kc < 4; kc++) {
        const int k0 = kc * 16;
        __syncthreads();     // aout complete (kc=0) / W chunk consumed
        // store prefetched proj_w chunk [128 cols][16 k] fp16 hi/lo, stride 24
#pragma unroll
        for (int it = 0; it < 2; it++) {
            float4 v = preg[it];
            u32 h01, l01, h23, l23;
            cvt_hl(make_float2(v.x, v.y), h01, l01);
            cvt_hl(make_float2(v.z, v.w), h23, l23);
            *(uint2*)(wh + pc[it] * 24 + 4 * pj4[it]) = make_uint2(h01, h23);
            *(uint2*)(wl + pc[it] * 24 + 4 * pj4[it]) = make_uint2(l01, l23);
        }
        __syncthreads();
        if (kc < 3) {
#pragma unroll
            for (int it = 0; it < 2; it++)
                preg[it] = *(const float4*)(psrc[it] + (kc + 1) * 16);
        }
        // A fragments from aout
        u32 ah[4], al[4];
        {
            float2 f00 = *(const float2*)(smem + SM_X + r0 * ASTR + k0 + 2 * t4);
            float2 f10 = *(const float2*)(smem + SM_X + (r0 + 8) * ASTR + k0 + 2 * t4);
            float2 f01 = *(const float2*)(smem + SM_X + r0 * ASTR + k0 + 8 + 2 * t4);
            float2 f11 = *(const float2*)(smem + SM_X + (r0 + 8) * ASTR + k0 + 8 + 2 * t4);
            cvt_hl(f00, ah[0], al[0]); cvt_hl(f10, ah[1], al[1]);
            cvt_hl(f01, ah[2], al[2]); cvt_hl(f11, ah[3], al[3]);
        }
#pragma unroll
        for (int nt = 0; nt < 8; nt++) {
            const int col = nh * 64 + nt * 8 + g;     // out channel
            u32 bh0 = *(const u32*)(wh + col * 24 + 2 * t4);
            u32 bh1 = *(const u32*)(wh + col * 24 + 2 * t4 + 8);
            u32 bl0 = *(const u32*)(wl + col * 24 + 2 * t4);
            u32 bl1 = *(const u32*)(wl + col * 24 + 2 * t4 + 8);
            mma16816(pacc[nt], ah[0], ah[1], ah[2], ah[3], bh0, bh1);
            mma16816(pacc[nt], ah[0], ah[1], ah[2], ah[3], bl0, bl1);
            mma16816(pacc[nt], al[0], al[1], al[2], al[3], bh0, bh1);
        }
    }

    // split-k accumulate into zero-initialized out
    float* og = out + (size_t)bwin * 64 * DIM;
#pragma unroll
    for (int nt = 0; nt < 8; nt++) {
        const int c0 = nh * 64 + nt * 8 + 2 * t4;
        float2 bb = make_float2(0.f, 0.f);
        if (cg == 0) { bb.x = proj_b[c0]; bb.y = proj_b[c0 + 1]; }
        atomicAdd(&og[r0 * DIM + c0],           pacc[nt][0] + bb.x);
        atomicAdd(&og[r0 * DIM + c0 + 1],       pacc[nt][1] + bb.y);
        atomicAdd(&og[(r0 + 8) * DIM + c0],     pacc[nt][2] + bb.x);
        atomicAdd(&og[(r0 + 8) * DIM + c0 + 1], pacc[nt][3] + bb.y);
    }
}

// ---------------------------------------------------------------------------
extern "C" void kernel_launch(void* const* d_in, const int* in_sizes, int n_in,
                              void* d_out, int out_size) {
    const float* x          = (const float*)d_in[0];
    const float* mask       = (const float*)d_in[1];
    const float* frame_type = (const float*)d_in[2];
    const float* qkv_w      = (const float*)d_in[3];
    const float* qkv_b      = (const float*)d_in[4];
    const float* table      = (const float*)d_in[5];
    const float* proj_w     = (const float*)d_in[6];
    const float* proj_b     = (const float*)d_in[7];
    const float* aff_w1     = (const float*)d_in[8];
    const float* aff_b1     = (const float*)d_in[9];
    const float* aff_w2     = (const float*)d_in[10];
    const int*   rel_index  = (const int*)d_in[11];
    float* out = (float*)d_out;

    cudaFuncSetAttribute(win_attn_kernel,
                         cudaFuncAttributeMaxDynamicSharedMemorySize, SMEM_BYTES);

    cudaMemsetAsync(out, 0, (size_t)out_size * sizeof(float));
    prep_kernel<<<129, 256>>>(frame_type, table, aff_w1, aff_b1, aff_w2, rel_index);
    win_attn_kernel<<<NWIN * 2, 256, SMEM_BYTES>>>(x, mask, qkv_w, qkv_b,
                                                   proj_w, proj_b, out);
}